// round 11
// baseline (speedup 1.0000x reference)
#include <cuda_runtime.h>
#include <cuda_bf16.h>
#include <cstdint>

#define N_NODES   100000
#define D_FEAT    128
#define HID       64
#define N_SAMPLES 250000

#define ROWS_CTA  256      // 128 HMMA rows + 128 FFMA rows per CTA
#define NBLOCKS   ((N_NODES + ROWS_CTA - 1) / ROWS_CTA)

// Merged per-node table (51.2 MB scratch).
// T[n][ 0: 64] = x1[n]@w1[0:128]   + x2[n]@w1[256:384] + b1   (src half)
// T[n][64:128] = x1[n]@w1[128:256] + x2[n]@w1[384:512]        (dst half)
__device__ float g_T[(size_t)N_NODES * 128];

// Pre-split B operand (HMMA path), chunk-major: [c][n 0..127][kk 0..63] bf16.
__device__ __nv_bfloat16 g_Bhi[4 * 128 * 64];
__device__ __nv_bfloat16 g_Blo[4 * 128 * 64];

__device__ int g_idx_is64;   // 1 if train_sample is int64, 0 if int32

// ---------------- helpers ----------------
__device__ __forceinline__ uint32_t smem_u32(const void* p) {
    uint32_t a;
    asm("{ .reg .u64 t; cvta.to.shared.u64 t, %1; cvt.u32.u64 %0, t; }"
        : "=r"(a) : "l"(p));
    return a;
}
__device__ __forceinline__ void ldmatrix_x4(uint32_t& r0, uint32_t& r1,
                                            uint32_t& r2, uint32_t& r3,
                                            uint32_t addr) {
    asm volatile("ldmatrix.sync.aligned.m8n8.x4.shared.b16 {%0,%1,%2,%3}, [%4];"
                 : "=r"(r0), "=r"(r1), "=r"(r2), "=r"(r3) : "r"(addr));
}
__device__ __forceinline__ void mma_bf16(float& d0, float& d1, float& d2, float& d3,
                                         uint32_t a0, uint32_t a1, uint32_t a2, uint32_t a3,
                                         uint32_t b0, uint32_t b1) {
    asm volatile(
        "mma.sync.aligned.m16n8k16.row.col.f32.bf16.bf16.f32 "
        "{%0,%1,%2,%3}, {%4,%5,%6,%7}, {%8,%9}, {%0,%1,%2,%3};"
        : "+f"(d0), "+f"(d1), "+f"(d2), "+f"(d3)
        : "r"(a0), "r"(a1), "r"(a2), "r"(a3), "r"(b0), "r"(b1));
}
__device__ __forceinline__ unsigned long long pack2(float lo, float hi) {
    unsigned long long r;
    asm("mov.b64 %0, {%1,%2};" : "=l"(r) : "f"(lo), "f"(hi));
    return r;
}
__device__ __forceinline__ unsigned long long fma2(unsigned long long a,
                                                   unsigned long long b,
                                                   unsigned long long c) {
    unsigned long long d;
    asm("fma.rn.f32x2 %0, %1, %2, %3;" : "=l"(d) : "l"(a), "l"(b), "l"(c));
    return d;
}
__device__ __forceinline__ float2 unpack2(unsigned long long v) {
    float2 r;
    asm("mov.b64 {%0,%1}, %2;" : "=f"(r.x), "=f"(r.y) : "l"(v));
    return r;
}

// ============================================================================
// Kernel 0: dtype detect (block 0) + B split (128 blocks, 1 elem/thread).
// ============================================================================
__global__ void prep_kernel(const unsigned int* __restrict__ ts32,
                            const float* __restrict__ w1)
{
    int t = threadIdx.x;

    if (blockIdx.x == 0) {
        __shared__ int nonzero;
        if (t == 0) nonzero = 0;
        __syncthreads();
        unsigned int acc = 0;
#pragma unroll
        for (int i = 0; i < 16; i++) acc |= ts32[2 * (t + 256 * i) + 1];
        if (acc) atomicOr(&nonzero, 1);
        __syncthreads();
        if (t == 0) g_idx_is64 = nonzero ? 0 : 1;
    }

    int idx = blockIdx.x * 256 + t;                // 0..32767
    int c  = idx >> 13;
    int n  = (idx >> 6) & 127;
    int kk = idx & 63;
    int gk = c * 64 + kk;
    int wrow = (n < 64) ? ((gk < 128) ? gk : gk + 128)
                        : ((gk < 128) ? gk + 128 : gk + 256);
    int wcol = n & 63;
    float v = w1[wrow * HID + wcol];
    __nv_bfloat16 h = __float2bfloat16_rn(v);
    __nv_bfloat16 l = __float2bfloat16_rn(v - __bfloat162float(h));
    g_Bhi[idx] = h;
    g_Blo[idx] = l;
}

// ============================================================================
// Kernel 1: DUAL-PIPE precompute GEMM. 512 threads.
// Warps 0-7  (t<256):  HMMA path (R10-exact) on rows [row0, row0+128).
// Warps 8-15 (t>=256): f32x2 FFMA path (R3) on rows [row0+128, row0+256).
// Every SMSP gets 2 HMMA + 2 FFMA warps -> tensor & fma pipes run together.
// Convergent barriers: per chunk, stage -> sync -> compute -> sync.
// ============================================================================
#define A_STRIDE  72                         // HMMA A: bf16/row 64+8 pad
#define AHI_OFF   0
#define ALO_OFF   18432
#define AS_OFF    36864                      // FFMA As: 128 x 68 f32
#define AS_STRIDE 68                         // padded: 2-way LDS conflicts max
#define BS_OFF    (AS_OFF + 128 * AS_STRIDE * 4)   // 71680; Bs: 64x128 f32
#define SMEM_TOT  (BS_OFF + 64 * 128 * 4)          // 104448 B

__global__ __launch_bounds__(512, 1)
void precompute_dual_kernel(const float* __restrict__ in1,
                            const float* __restrict__ in2,
                            const float* __restrict__ w1,
                            const float* __restrict__ b1)
{
    extern __shared__ char smem[];
    __nv_bfloat16* Ahi = (__nv_bfloat16*)(smem + AHI_OFF);
    __nv_bfloat16* Alo = (__nv_bfloat16*)(smem + ALO_OFF);
    float*         As  = (float*)(smem + AS_OFF);
    float*         Bs  = (float*)(smem + BS_OFF);

    const int t     = threadIdx.x;
    const bool hside = (t < 256);
    const int row0h = blockIdx.x * ROWS_CTA;
    const int row0f = row0h + 128;

    // ---------------- HMMA-side persistent state ----------------
    const int th     = t & 255;
    const int wid    = th >> 5;
    const int lane   = t & 31;
    const int warp_m = wid & 1;
    const int warp_n = wid >> 1;
    const uint32_t ahi_base = smem_u32(Ahi);
    const uint32_t alo_base = smem_u32(Alo);
    const int lm_row  = lane & 15;
    const int lm_koff = (lane >> 4) * 16;
    float hacc[4][4][4];

    // ---------------- FFMA-side persistent state ----------------
    const int t2 = t & 255;
    const int tm = t2 >> 4;
    const int tn = t2 & 15;
    unsigned long long facc[8][4];

    if (hside) {
#pragma unroll
        for (int mt = 0; mt < 4; mt++)
#pragma unroll
            for (int nt = 0; nt < 4; nt++)
#pragma unroll
                for (int r = 0; r < 4; r++) hacc[mt][nt][r] = 0.f;
    } else {
#pragma unroll
        for (int i = 0; i < 8; i++)
#pragma unroll
            for (int j = 0; j < 4; j++) facc[i][j] = 0ULL;
    }

    for (int c = 0; c < 4; c++) {
        if (c) __syncthreads();

        const float* __restrict__ in = (c < 2) ? in1 : in2;
        const int col0 = (c & 1) * 64;

        if (hside) {
            // ---- stage HMMA A chunk: fp32 -> bf16 hi/lo, padded rows ----
#pragma unroll
            for (int i = 0; i < 8; i++) {
                int linear = th + 256 * i;          // 0..2047
                int r  = linear >> 4;
                int c4 = linear & 15;
                int grow = row0h + r;
                float4 v = make_float4(0.f, 0.f, 0.f, 0.f);
                if (grow < N_NODES)
                    v = *(const float4*)&in[(size_t)grow * D_FEAT + col0 + 4 * c4];
                __nv_bfloat16 h0 = __float2bfloat16_rn(v.x), h1 = __float2bfloat16_rn(v.y);
                __nv_bfloat16 h2 = __float2bfloat16_rn(v.z), h3 = __float2bfloat16_rn(v.w);
                __nv_bfloat16 l0 = __float2bfloat16_rn(v.x - __bfloat162float(h0));
                __nv_bfloat16 l1 = __float2bfloat16_rn(v.y - __bfloat162float(h1));
                __nv_bfloat16 l2 = __float2bfloat16_rn(v.z - __bfloat162float(h2));
                __nv_bfloat16 l3 = __float2bfloat16_rn(v.w - __bfloat162float(h3));
                __nv_bfloat162 hp0 = {h0, h1}, hp1 = {h2, h3};
                __nv_bfloat162 lp0 = {l0, l1}, lp1 = {l2, l3};
                int off = r * A_STRIDE + 4 * c4;
                *(uint2*)&Ahi[off] = make_uint2(*(uint32_t*)&hp0, *(uint32_t*)&hp1);
                *(uint2*)&Alo[off] = make_uint2(*(uint32_t*)&lp0, *(uint32_t*)&lp1);
            }
        } else {
            // ---- stage FFMA As (fp32 rows) + Bs (w1 chunk) ----
#pragma unroll
            for (int i = 0; i < 8; i++) {
                int linear = t2 + 256 * i;          // 0..2047
                int r  = linear >> 4;
                int c4 = linear & 15;
                int grow = row0f + r;
                float4 v = make_float4(0.f, 0.f, 0.f, 0.f);
                if (grow < N_NODES)
                    v = *(const float4*)&in[(size_t)grow * D_FEAT + col0 + 4 * c4];
                *(float4*)&As[r * AS_STRIDE + 4 * c4] = v;
            }
#pragma unroll
            for (int i = 0; i < 8; i++) {
                int linear = t2 + 256 * i;
                int kk = linear >> 5;               // 0..63
                int c4 = linear & 31;               // 0..31
                int gk = c * 64 + kk;
                int wrow, wcol;
                if (c4 < 16) { wrow = (gk < 128) ? gk : gk + 128; wcol = 4 * c4; }
                else         { wrow = (gk < 128) ? gk + 128 : gk + 256; wcol = 4 * (c4 - 16); }
                float4 v = *(const float4*)&w1[wrow * HID + wcol];
                *(float4*)&Bs[kk * 128 + 4 * c4] = v;
            }
        }
        __syncthreads();

        if (hside) {
            // ---- HMMA compute (R10-exact) ----
            const uint32_t* __restrict__ bhp = (const uint32_t*)(g_Bhi + c * 8192);
            const uint32_t* __restrict__ blp = (const uint32_t*)(g_Blo + c * 8192);
            const int bq = lane & 3;
#pragma unroll
            for (int ks = 0; ks < 4; ks++) {
                const int k0 = ks * 16;
                uint32_t ah[4][4], al[4][4];
#pragma unroll
                for (int mt = 0; mt < 4; mt++) {
                    int m = warp_m * 64 + mt * 16 + lm_row;
                    uint32_t byteoff = (uint32_t)(m * (A_STRIDE * 2) + k0 * 2 + lm_koff);
                    ldmatrix_x4(ah[mt][0], ah[mt][1], ah[mt][2], ah[mt][3],
                                ahi_base + byteoff);
                    ldmatrix_x4(al[mt][0], al[mt][1], al[mt][2], al[mt][3],
                                alo_base + byteoff);
                }
                uint32_t bh[4][2], bl[4][2];
#pragma unroll
                for (int nt = 0; nt < 4; nt++) {
                    int n = warp_n * 32 + nt * 8 + (lane >> 2);
                    int base = n * 32 + (k0 >> 1) + bq;
                    bh[nt][0] = bhp[base];
                    bh[nt][1] = bhp[base + 4];
                    bl[nt][0] = blp[base];
                    bl[nt][1] = blp[base + 4];
                }
#pragma unroll
                for (int mt = 0; mt < 4; mt++)
#pragma unroll
                    for (int nt = 0; nt < 4; nt++) {
                        float* d = hacc[mt][nt];
                        mma_bf16(d[0], d[1], d[2], d[3],
                                 ah[mt][0], ah[mt][1], ah[mt][2], ah[mt][3],
                                 bh[nt][0], bh[nt][1]);
                        mma_bf16(d[0], d[1], d[2], d[3],
                                 ah[mt][0], ah[mt][1], ah[mt][2], ah[mt][3],
                                 bl[nt][0], bl[nt][1]);
                        mma_bf16(d[0], d[1], d[2], d[3],
                                 al[mt][0], al[mt][1], al[mt][2], al[mt][3],
                                 bh[nt][0], bh[nt][1]);
                    }
            }
        } else {
            // ---- FFMA compute (f32x2). Strided row map: rows tm+16i ----
#pragma unroll
            for (int k = 0; k < 64; k += 2) {
                float2 af[8];
#pragma unroll
                for (int i = 0; i < 4; i++) {
                    af[i]     = *(const float2*)&As[(tm + 16 * i) * AS_STRIDE + k];
                    af[i + 4] = *(const float2*)&As[(64 + tm + 16 * i) * AS_STRIDE + k];
                }
#pragma unroll
                for (int kq = 0; kq < 2; kq++) {
                    ulonglong2 blo = *(const ulonglong2*)&Bs[(k + kq) * 128 + tn * 4];
                    ulonglong2 bhi = *(const ulonglong2*)&Bs[(k + kq) * 128 + 64 + tn * 4];
                    unsigned long long bp0 = blo.x, bp1 = blo.y;
                    unsigned long long bp2 = bhi.x, bp3 = bhi.y;
#pragma unroll
                    for (int i = 0; i < 8; i++) {
                        float a = kq ? af[i].y : af[i].x;
                        unsigned long long ap = pack2(a, a);
                        facc[i][0] = fma2(ap, bp0, facc[i][0]);
                        facc[i][1] = fma2(ap, bp1, facc[i][1]);
                        facc[i][2] = fma2(ap, bp2, facc[i][2]);
                        facc[i][3] = fma2(ap, bp3, facc[i][3]);
                    }
                }
            }
        }
    }

    // ---------------- epilogues (register -> global, no smem) ----------------
    if (hside) {
        const int crow = lane >> 2;
        const int ccol = (lane & 3) * 2;
#pragma unroll
        for (int nt = 0; nt < 4; nt++) {
            int col = warp_n * 32 + nt * 8 + ccol;
            float2 bv = make_float2(0.f, 0.f);
            if (col < 64) bv = *(const float2*)&b1[col];
#pragma unroll
            for (int mt = 0; mt < 4; mt++) {
                int m = warp_m * 64 + mt * 16 + crow;
                int grow0 = row0h + m;
                int grow1 = grow0 + 8;
                float* d = hacc[mt][nt];
                if (grow0 < N_NODES)
                    *(float2*)&g_T[(size_t)grow0 * 128 + col] =
                        make_float2(d[0] + bv.x, d[1] + bv.y);
                if (grow1 < N_NODES)
                    *(float2*)&g_T[(size_t)grow1 * 128 + col] =
                        make_float2(d[2] + bv.x, d[3] + bv.y);
            }
        }
    } else {
        const float4 bias = *(const float4*)&b1[tn * 4];
#pragma unroll
        for (int i = 0; i < 8; i++) {
            int m = (i < 4) ? (tm + 16 * i) : (64 + tm + 16 * (i - 4));
            int grow = row0f + m;
            if (grow < N_NODES) {
                float2 c0 = unpack2(facc[i][0]);
                float2 c1 = unpack2(facc[i][1]);
                float2 c2 = unpack2(facc[i][2]);
                float2 c3 = unpack2(facc[i][3]);
                *(float4*)&g_T[(size_t)grow * 128 + tn * 4] =
                    make_float4(c0.x + bias.x, c0.y + bias.y,
                                c1.x + bias.z, c1.y + bias.w);
                *(float4*)&g_T[(size_t)grow * 128 + 64 + tn * 4] =
                    make_float4(c2.x, c2.y, c3.x, c3.y);
            }
        }
    }
}

// ============================================================================
// Kernel 2: gather + head. Half-warp per sample; lane l -> float4 of hidden.
// ============================================================================
__global__ __launch_bounds__(256)
void gather_kernel(const void* __restrict__ ts_raw,
                   const float* __restrict__ w2,
                   float* __restrict__ out, int n)
{
    int hs   = (blockIdx.x * blockDim.x + threadIdx.x) >> 4;
    int lane = threadIdx.x & 15;
    if (hs >= n) return;

    long long src, dst;
    if (g_idx_is64) {
        longlong2 sd = ((const longlong2*)ts_raw)[hs];
        src = sd.x; dst = sd.y;
    } else {
        int2 sd = ((const int2*)ts_raw)[hs];
        src = sd.x; dst = sd.y;
    }
    src = min(max(src, 0LL), (long long)(N_NODES - 1));
    dst = min(max(dst, 0LL), (long long)(N_NODES - 1));

    float4 s = *(const float4*)(g_T + (size_t)src * 128 + 4 * lane);
    float4 d = *(const float4*)(g_T + (size_t)dst * 128 + 64 + 4 * lane);
    float4 w = ((const float4*)w2)[lane];

    float p = fmaxf(s.x + d.x, 0.f) * w.x
            + fmaxf(s.y + d.y, 0.f) * w.y
            + fmaxf(s.z + d.z, 0.f) * w.z
            + fmaxf(s.w + d.w, 0.f) * w.w;

#pragma unroll
    for (int off = 8; off; off >>= 1)
        p += __shfl_xor_sync(0xffffffffu, p, off);

    if (lane == 0) out[hs] = p;
}

// ============================================================================
extern "C" void kernel_launch(void* const* d_in, const int* in_sizes, int n_in,
                              void* d_out, int out_size)
{
    const float* in1 = (const float*)d_in[0];      // (100000,128) f32
    const float* in2 = (const float*)d_in[1];      // (100000,128) f32
    const void*  ts  = d_in[2];                    // (250000,2) int32/int64
    const float* w1  = (const float*)d_in[3];      // (512,64) f32
    const float* b1  = (const float*)d_in[4];      // (64,)   f32
    const float* w2  = (const float*)d_in[5];      // (64,1)  f32
    float*       out = (float*)d_out;              // (250000,1) f32

    (void)in_sizes; (void)n_in; (void)out_size;

    prep_kernel<<<128, 256>>>((const unsigned int*)ts, w1);

    cudaFuncSetAttribute(precompute_dual_kernel,
                         cudaFuncAttributeMaxDynamicSharedMemorySize, SMEM_TOT);
    precompute_dual_kernel<<<NBLOCKS, 512, SMEM_TOT>>>(in1, in2, w1, b1);

    int samples_per_block = 256 / 16;   // 16 samples per 256-thread block
    int blocks = (N_SAMPLES + samples_per_block - 1) / samples_per_block;
    gather_kernel<<<blocks, 256>>>(ts, w2, out, N_SAMPLES);
}

// round 12
// speedup vs baseline: 1.2988x; 1.2988x over previous
#include <cuda_runtime.h>
#include <cuda_fp16.h>
#include <cstdint>

#define N_NODES   100000
#define D_FEAT    128
#define HID       64
#define N_SAMPLES 250000

// Merged per-node table (51.2 MB scratch).
// T[n][ 0: 64] = x1[n]@w1[0:128]   + x2[n]@w1[256:384] + b1   (src half)
// T[n][64:128] = x1[n]@w1[128:256] + x2[n]@w1[384:512]        (dst half)
__device__ float g_T[(size_t)N_NODES * 128];

// B operand in fp16 (|w1| <= 0.108 -> full 11-bit mantissa; rounding ~2^-12).
// Chunk-major: [chunk c][n 0..127][kk 0..63].
__device__ __half g_Bf[4 * 128 * 64];

__device__ int g_idx_is64;   // 1 if train_sample is int64, 0 if int32

// ---------------- helpers ----------------
__device__ __forceinline__ uint32_t smem_u32(const void* p) {
    uint32_t a;
    asm("{ .reg .u64 t; cvta.to.shared.u64 t, %1; cvt.u32.u64 %0, t; }"
        : "=r"(a) : "l"(p));
    return a;
}
__device__ __forceinline__ void ldmatrix_x4(uint32_t& r0, uint32_t& r1,
                                            uint32_t& r2, uint32_t& r3,
                                            uint32_t addr) {
    asm volatile("ldmatrix.sync.aligned.m8n8.x4.shared.b16 {%0,%1,%2,%3}, [%4];"
                 : "=r"(r0), "=r"(r1), "=r"(r2), "=r"(r3) : "r"(addr));
}
__device__ __forceinline__ void mma_f16(float& d0, float& d1, float& d2, float& d3,
                                        uint32_t a0, uint32_t a1, uint32_t a2, uint32_t a3,
                                        uint32_t b0, uint32_t b1) {
    asm volatile(
        "mma.sync.aligned.m16n8k16.row.col.f32.f16.f16.f32 "
        "{%0,%1,%2,%3}, {%4,%5,%6,%7}, {%8,%9}, {%0,%1,%2,%3};"
        : "+f"(d0), "+f"(d1), "+f"(d2), "+f"(d3)
        : "r"(a0), "r"(a1), "r"(a2), "r"(a3), "r"(b0), "r"(b1));
}

// ============================================================================
// Kernel 0: dtype detect (block 0) + B fp16 convert (128 blocks, 1 elem/thr).
// B[c][n][kk] = w1[wrow][wcol], gk = 64c + kk:
//   n<64 : wrow = gk<128 ? gk     : gk+128 ; wcol = n
//   n>=64: wrow = gk<128 ? gk+128 : gk+256 ; wcol = n-64
// ============================================================================
__global__ void prep_kernel(const unsigned int* __restrict__ ts32,
                            const float* __restrict__ w1)
{
    int t = threadIdx.x;

    if (blockIdx.x == 0) {
        __shared__ int nonzero;
        if (t == 0) nonzero = 0;
        __syncthreads();
        unsigned int acc = 0;
#pragma unroll
        for (int i = 0; i < 16; i++) acc |= ts32[2 * (t + 256 * i) + 1];
        if (acc) atomicOr(&nonzero, 1);
        __syncthreads();
        if (t == 0) g_idx_is64 = nonzero ? 0 : 1;
    }

    int idx = blockIdx.x * 256 + t;                // 0..32767
    int c  = idx >> 13;
    int n  = (idx >> 6) & 127;
    int kk = idx & 63;
    int gk = c * 64 + kk;
    int wrow = (n < 64) ? ((gk < 128) ? gk : gk + 128)
                        : ((gk < 128) ? gk + 128 : gk + 256);
    int wcol = n & 63;
    g_Bf[idx] = __float2half_rn(w1[wrow * HID + wcol]);
}

// ============================================================================
// Kernel 1: warp-MMA precompute GEMM — fp16 A-split, 2 terms (R10 structure).
// D = (Ah + Al) * B_f16 ;  Ah = f16(A), Al = f16(A - Ah).
// CTA: 256 threads (8 warps), 128M x 128N, K=256 in four 64-chunks.
// Warp tile 64x32 (4x4 m16n8 tiles). A via padded smem + ldmatrix; B frags
// straight from fp16 global scratch (L1-resident, shared by all CTAs).
// ============================================================================
#define A_STRIDE 72   // fp16 elems per smem row (64 data + 8 pad), 144 B

__global__ __launch_bounds__(256, 1)
void precompute_mma_kernel(const float* __restrict__ in1,
                           const float* __restrict__ in2,
                           const float* __restrict__ b1)
{
    __shared__ __half Ahi[128 * A_STRIDE];
    __shared__ __half Alo[128 * A_STRIDE];

    const int t      = threadIdx.x;
    const int wid    = t >> 5;
    const int lane   = t & 31;
    const int warp_m = wid & 1;          // 0..1  (64-row halves)
    const int warp_n = wid >> 1;         // 0..3  (32-col quarters)
    const int row0   = blockIdx.x * 128;

    const uint32_t ahi_base = smem_u32(Ahi);
    const uint32_t alo_base = smem_u32(Alo);

    float acc[4][4][4];
#pragma unroll
    for (int mt = 0; mt < 4; mt++)
#pragma unroll
        for (int nt = 0; nt < 4; nt++)
#pragma unroll
            for (int r = 0; r < 4; r++) acc[mt][nt][r] = 0.f;

    const int lm_row  = lane & 15;            // row offset within 16-row tile
    const int lm_koff = (lane >> 4) * 16;     // byte offset: k half

    for (int c = 0; c < 4; c++) {
        if (c) __syncthreads();               // protect smem reuse

        // ---- stage A chunk: load fp32, split fp16 hi/lo, store ----
        const float* __restrict__ in = (c < 2) ? in1 : in2;
        const int col0 = (c & 1) * 64;
#pragma unroll
        for (int i = 0; i < 8; i++) {
            int linear = t + 256 * i;          // 0..2047 float4 slots
            int r  = linear >> 4;              // row 0..127
            int c4 = linear & 15;              // float4 slot along k
            int grow = row0 + r;
            float4 v = make_float4(0.f, 0.f, 0.f, 0.f);
            if (grow < N_NODES)
                v = *(const float4*)&in[(size_t)grow * D_FEAT + col0 + 4 * c4];
            __half h0 = __float2half_rn(v.x), h1 = __float2half_rn(v.y);
            __half h2 = __float2half_rn(v.z), h3 = __float2half_rn(v.w);
            __half l0 = __float2half_rn(v.x - __half2float(h0));
            __half l1 = __float2half_rn(v.y - __half2float(h1));
            __half l2 = __float2half_rn(v.z - __half2float(h2));
            __half l3 = __float2half_rn(v.w - __half2float(h3));
            __half2 hp0 = {h0, h1}, hp1 = {h2, h3};
            __half2 lp0 = {l0, l1}, lp1 = {l2, l3};
            int off = r * A_STRIDE + 4 * c4;
            *(uint2*)&Ahi[off] = make_uint2(*(uint32_t*)&hp0, *(uint32_t*)&hp1);
            *(uint2*)&Alo[off] = make_uint2(*(uint32_t*)&lp0, *(uint32_t*)&lp1);
        }
        __syncthreads();

        // ---- B fragment base pointer for this chunk (single fp16 matrix) ----
        const uint32_t* __restrict__ bfp = (const uint32_t*)(g_Bf + c * 8192);
        const int bq = lane & 3;              // k-pair slot within frag

#pragma unroll
        for (int ks = 0; ks < 4; ks++) {
            const int k0 = ks * 16;

            // A fragments: 4 m-tiles x (hi,lo), ldmatrix.x4 each
            uint32_t ah[4][4], al[4][4];
#pragma unroll
            for (int mt = 0; mt < 4; mt++) {
                int m = warp_m * 64 + mt * 16 + lm_row;
                uint32_t byteoff = (uint32_t)(m * (A_STRIDE * 2) + k0 * 2 + lm_koff);
                ldmatrix_x4(ah[mt][0], ah[mt][1], ah[mt][2], ah[mt][3],
                            ahi_base + byteoff);
                ldmatrix_x4(al[mt][0], al[mt][1], al[mt][2], al[mt][3],
                            alo_base + byteoff);
            }
            // B fragments: 4 n-tiles, direct 32-bit loads (L1 hits)
            uint32_t bf[4][2];
#pragma unroll
            for (int nt = 0; nt < 4; nt++) {
                int n = warp_n * 32 + nt * 8 + (lane >> 2);
                int base = n * 32 + (k0 >> 1) + bq;
                bf[nt][0] = bfp[base];
                bf[nt][1] = bfp[base + 4];
            }
            // MMA: Ah*B + Al*B (2 terms)
#pragma unroll
            for (int mt = 0; mt < 4; mt++)
#pragma unroll
                for (int nt = 0; nt < 4; nt++) {
                    float* d = acc[mt][nt];
                    mma_f16(d[0], d[1], d[2], d[3],
                            ah[mt][0], ah[mt][1], ah[mt][2], ah[mt][3],
                            bf[nt][0], bf[nt][1]);
                    mma_f16(d[0], d[1], d[2], d[3],
                            al[mt][0], al[mt][1], al[mt][2], al[mt][3],
                            bf[nt][0], bf[nt][1]);
                }
        }
    }

    // ---- epilogue: add bias to cols<64, store float2 pairs ----
    const int crow = lane >> 2;               // 0..7
    const int ccol = (lane & 3) * 2;          // 0,2,4,6
#pragma unroll
    for (int nt = 0; nt < 4; nt++) {
        int col = warp_n * 32 + nt * 8 + ccol;
        float2 bv = make_float2(0.f, 0.f);
        if (col < 64) bv = *(const float2*)&b1[col];
#pragma unroll
        for (int mt = 0; mt < 4; mt++) {
            int m = warp_m * 64 + mt * 16 + crow;
            int grow0 = row0 + m;
            int grow1 = grow0 + 8;
            float* d = acc[mt][nt];
            if (grow0 < N_NODES)
                *(float2*)&g_T[(size_t)grow0 * 128 + col] =
                    make_float2(d[0] + bv.x, d[1] + bv.y);
            if (grow1 < N_NODES)
                *(float2*)&g_T[(size_t)grow1 * 128 + col] =
                    make_float2(d[2] + bv.x, d[3] + bv.y);
        }
    }
}

// ============================================================================
// Kernel 2: gather + head. Half-warp per sample; lane l -> float4 of hidden.
// ============================================================================
__global__ __launch_bounds__(256)
void gather_kernel(const void* __restrict__ ts_raw,
                   const float* __restrict__ w2,
                   float* __restrict__ out, int n)
{
    int hs   = (blockIdx.x * blockDim.x + threadIdx.x) >> 4;
    int lane = threadIdx.x & 15;
    if (hs >= n) return;

    long long src, dst;
    if (g_idx_is64) {
        longlong2 sd = ((const longlong2*)ts_raw)[hs];
        src = sd.x; dst = sd.y;
    } else {
        int2 sd = ((const int2*)ts_raw)[hs];
        src = sd.x; dst = sd.y;
    }
    src = min(max(src, 0LL), (long long)(N_NODES - 1));
    dst = min(max(dst, 0LL), (long long)(N_NODES - 1));

    float4 s = *(const float4*)(g_T + (size_t)src * 128 + 4 * lane);
    float4 d = *(const float4*)(g_T + (size_t)dst * 128 + 64 + 4 * lane);
    float4 w = ((const float4*)w2)[lane];

    float p = fmaxf(s.x + d.x, 0.f) * w.x
            + fmaxf(s.y + d.y, 0.f) * w.y
            + fmaxf(s.z + d.z, 0.f) * w.z
            + fmaxf(s.w + d.w, 0.f) * w.w;

#pragma unroll
    for (int off = 8; off; off >>= 1)
        p += __shfl_xor_sync(0xffffffffu, p, off);

    if (lane == 0) out[hs] = p;
}

// ============================================================================
extern "C" void kernel_launch(void* const* d_in, const int* in_sizes, int n_in,
                              void* d_out, int out_size)
{
    const float* in1 = (const float*)d_in[0];      // (100000,128) f32
    const float* in2 = (const float*)d_in[1];      // (100000,128) f32
    const void*  ts  = d_in[2];                    // (250000,2) int32/int64
    const float* w1  = (const float*)d_in[3];      // (512,64) f32
    const float* b1  = (const float*)d_in[4];      // (64,)   f32
    const float* w2  = (const float*)d_in[5];      // (64,1)  f32
    float*       out = (float*)d_out;              // (250000,1) f32

    (void)in_sizes; (void)n_in; (void)out_size;

    prep_kernel<<<128, 256>>>((const unsigned int*)ts, w1);

    precompute_mma_kernel<<<(N_NODES + 127) / 128, 256>>>(in1, in2, b1);

    int samples_per_block = 256 / 16;   // 16 samples per 256-thread block
    int blocks = (N_SAMPLES + samples_per_block - 1) / samples_per_block;
    gather_kernel<<<blocks, 256>>>(ts, w2, out, N_SAMPLES);
}

// round 13
// speedup vs baseline: 1.5303x; 1.1782x over previous
#include <cuda_runtime.h>
#include <cstdint>

#define N_NODES   100000
#define D_FEAT    128
#define HID       64
#define N_SAMPLES 250000

// Merged per-node table (51.2 MB scratch).
// T[n][ 0: 64] = x1[n]@w1[0:128]   + x2[n]@w1[256:384] + b1   (src half)
// T[n][64:128] = x1[n]@w1[128:256] + x2[n]@w1[384:512]        (dst half)
__device__ float g_T[(size_t)N_NODES * 128];

// B operand, tf32-rounded fp32. Chunk-major: [chunk c][n 0..127][kk 0..63].
__device__ float g_Bt[4 * 128 * 64];

__device__ int g_idx_is64;   // 1 if train_sample is int64, 0 if int32

// ---------------- helpers ----------------
__device__ __forceinline__ uint32_t f2tf32(float f) {
    uint32_t r;
    asm("cvt.rna.tf32.f32 %0, %1;" : "=r"(r) : "f"(f));
    return r;
}
__device__ __forceinline__ void mma_tf32(float& d0, float& d1, float& d2, float& d3,
                                         uint32_t a0, uint32_t a1, uint32_t a2, uint32_t a3,
                                         uint32_t b0, uint32_t b1) {
    asm volatile(
        "mma.sync.aligned.m16n8k8.row.col.f32.tf32.tf32.f32 "
        "{%0,%1,%2,%3}, {%4,%5,%6,%7}, {%8,%9}, {%0,%1,%2,%3};"
        : "+f"(d0), "+f"(d1), "+f"(d2), "+f"(d3)
        : "r"(a0), "r"(a1), "r"(a2), "r"(a3), "r"(b0), "r"(b1));
}

// ============================================================================
// Kernel 0: dtype detect (block 0) + B tf32 convert (128 blocks, 1 elem/thr).
// B[c][n][kk] = tf32(w1[wrow][wcol]), gk = 64c + kk:
//   n<64 : wrow = gk<128 ? gk     : gk+128 ; wcol = n
//   n>=64: wrow = gk<128 ? gk+128 : gk+256 ; wcol = n-64
// ============================================================================
__global__ void prep_kernel(const unsigned int* __restrict__ ts32,
                            const float* __restrict__ w1)
{
    int t = threadIdx.x;

    if (blockIdx.x == 0) {
        __shared__ int nonzero;
        if (t == 0) nonzero = 0;
        __syncthreads();
        unsigned int acc = 0;
#pragma unroll
        for (int i = 0; i < 16; i++) acc |= ts32[2 * (t + 256 * i) + 1];
        if (acc) atomicOr(&nonzero, 1);
        __syncthreads();
        if (t == 0) g_idx_is64 = nonzero ? 0 : 1;
    }

    int idx = blockIdx.x * 256 + t;                // 0..32767
    int c  = idx >> 13;
    int n  = (idx >> 6) & 127;
    int kk = idx & 63;
    int gk = c * 64 + kk;
    int wrow = (n < 64) ? ((gk < 128) ? gk : gk + 128)
                        : ((gk < 128) ? gk + 128 : gk + 256);
    int wcol = n & 63;
    uint32_t v = f2tf32(w1[wrow * HID + wcol]);
    g_Bt[idx] = __uint_as_float(v);
}

// ============================================================================
// Kernel 1: warp-MMA precompute GEMM — tf32 single-term (R10 structure).
// CTA: 256 threads (8 warps), 128M x 128N, K=256 in four 64-chunks.
// Warp tile 64x32 (4x4 m16n8k8 tiles). A staged fp32 (tf32-rounded) in smem,
// stride-68 rows (conflict-free for the tf32 fragment pattern). B frags
// direct 32-bit LDGs from the tf32 global table (L1-resident).
// ============================================================================
#define AS_STRIDE 68   // fp32 elems per smem row (64 data + 4 pad)

__global__ __launch_bounds__(256, 1)
void precompute_mma_kernel(const float* __restrict__ in1,
                           const float* __restrict__ in2,
                           const float* __restrict__ b1)
{
    __shared__ float Atf[128 * AS_STRIDE];     // 34816 B

    const int t      = threadIdx.x;
    const int wid    = t >> 5;
    const int lane   = t & 31;
    const int warp_m = wid & 1;          // 0..1  (64-row halves)
    const int warp_n = wid >> 1;         // 0..3  (32-col quarters)
    const int row0   = blockIdx.x * 128;

    float acc[4][4][4];
#pragma unroll
    for (int mt = 0; mt < 4; mt++)
#pragma unroll
        for (int nt = 0; nt < 4; nt++)
#pragma unroll
            for (int r = 0; r < 4; r++) acc[mt][nt][r] = 0.f;

    const int arow = lane >> 2;               // 0..7 fragment row component
    const int acol = lane & 3;                // 0..3 fragment col component

    for (int c = 0; c < 4; c++) {
        if (c) __syncthreads();               // protect smem reuse

        // ---- stage A chunk: load fp32, tf32-round, store ----
        const float* __restrict__ in = (c < 2) ? in1 : in2;
        const int col0 = (c & 1) * 64;
#pragma unroll
        for (int i = 0; i < 8; i++) {
            int linear = t + 256 * i;          // 0..2047 float4 slots
            int r  = linear >> 4;              // row 0..127
            int c4 = linear & 15;              // float4 slot along k
            int grow = row0 + r;
            float4 v = make_float4(0.f, 0.f, 0.f, 0.f);
            if (grow < N_NODES)
                v = *(const float4*)&in[(size_t)grow * D_FEAT + col0 + 4 * c4];
            uint4 w;
            w.x = f2tf32(v.x); w.y = f2tf32(v.y);
            w.z = f2tf32(v.z); w.w = f2tf32(v.w);
            *(uint4*)&Atf[r * AS_STRIDE + 4 * c4] = w;
        }
        __syncthreads();

        const uint32_t* __restrict__ Au = (const uint32_t*)Atf;
        const uint32_t* __restrict__ Bu = (const uint32_t*)(g_Bt + c * 8192);

#pragma unroll
        for (int ks = 0; ks < 8; ks++) {
            const int k0 = ks * 8;

            // A fragments: 4 m-tiles, m16n8k8 tf32 layout
            uint32_t a[4][4];
#pragma unroll
            for (int mt = 0; mt < 4; mt++) {
                int row = warp_m * 64 + mt * 16 + arow;
                int base = row * AS_STRIDE + k0 + acol;
                a[mt][0] = Au[base];
                a[mt][1] = Au[base + 8 * AS_STRIDE];
                a[mt][2] = Au[base + 4];
                a[mt][3] = Au[base + 8 * AS_STRIDE + 4];
            }
            // B fragments: 4 n-tiles, direct 32-bit loads (L1 hits)
            uint32_t b[4][2];
#pragma unroll
            for (int nt = 0; nt < 4; nt++) {
                int n = warp_n * 32 + nt * 8 + arow;
                int base = n * 64 + k0 + acol;
                b[nt][0] = Bu[base];
                b[nt][1] = Bu[base + 4];
            }
            // MMA: single tf32 term
#pragma unroll
            for (int mt = 0; mt < 4; mt++)
#pragma unroll
                for (int nt = 0; nt < 4; nt++) {
                    float* d = acc[mt][nt];
                    mma_tf32(d[0], d[1], d[2], d[3],
                             a[mt][0], a[mt][1], a[mt][2], a[mt][3],
                             b[nt][0], b[nt][1]);
                }
        }
    }

    // ---- epilogue: add bias to cols<64, store float2 pairs ----
    const int crow = lane >> 2;               // 0..7
    const int ccol = (lane & 3) * 2;          // 0,2,4,6
#pragma unroll
    for (int nt = 0; nt < 4; nt++) {
        int col = warp_n * 32 + nt * 8 + ccol;
        float2 bv = make_float2(0.f, 0.f);
        if (col < 64) bv = *(const float2*)&b1[col];
#pragma unroll
        for (int mt = 0; mt < 4; mt++) {
            int m = warp_m * 64 + mt * 16 + crow;
            int grow0 = row0 + m;
            int grow1 = grow0 + 8;
            float* d = acc[mt][nt];
            if (grow0 < N_NODES)
                *(float2*)&g_T[(size_t)grow0 * 128 + col] =
                    make_float2(d[0] + bv.x, d[1] + bv.y);
            if (grow1 < N_NODES)
                *(float2*)&g_T[(size_t)grow1 * 128 + col] =
                    make_float2(d[2] + bv.x, d[3] + bv.y);
        }
    }
}

// ============================================================================
// Kernel 2: gather + head. Half-warp per sample; lane l -> float4 of hidden.
// ============================================================================
__global__ __launch_bounds__(256)
void gather_kernel(const void* __restrict__ ts_raw,
                   const float* __restrict__ w2,
                   float* __restrict__ out, int n)
{
    int hs   = (blockIdx.x * blockDim.x + threadIdx.x) >> 4;
    int lane = threadIdx.x & 15;
    if (hs >= n) return;

    long long src, dst;
    if (g_idx_is64) {
        longlong2 sd = ((const longlong2*)ts_raw)[hs];
        src = sd.x; dst = sd.y;
    } else {
        int2 sd = ((const int2*)ts_raw)[hs];
        src = sd.x; dst = sd.y;
    }
    src = min(max(src, 0LL), (long long)(N_NODES - 1));
    dst = min(max(dst, 0LL), (long long)(N_NODES - 1));

    float4 s = *(const float4*)(g_T + (size_t)src * 128 + 4 * lane);
    float4 d = *(const float4*)(g_T + (size_t)dst * 128 + 64 + 4 * lane);
    float4 w = ((const float4*)w2)[lane];

    float p = fmaxf(s.x + d.x, 0.f) * w.x
            + fmaxf(s.y + d.y, 0.f) * w.y
            + fmaxf(s.z + d.z, 0.f) * w.z
            + fmaxf(s.w + d.w, 0.f) * w.w;

#pragma unroll
    for (int off = 8; off; off >>= 1)
        p += __shfl_xor_sync(0xffffffffu, p, off);

    if (lane == 0) out[hs] = p;
}

// ============================================================================
extern "C" void kernel_launch(void* const* d_in, const int* in_sizes, int n_in,
                              void* d_out, int out_size)
{
    const float* in1 = (const float*)d_in[0];      // (100000,128) f32
    const float* in2 = (const float*)d_in[1];      // (100000,128) f32
    const void*  ts  = d_in[2];                    // (250000,2) int32/int64
    const float* w1  = (const float*)d_in[3];      // (512,64) f32
    const float* b1  = (const float*)d_in[4];      // (64,)   f32
    const float* w2  = (const float*)d_in[5];      // (64,1)  f32
    float*       out = (float*)d_out;              // (250000,1) f32

    (void)in_sizes; (void)n_in; (void)out_size;

    prep_kernel<<<128, 256>>>((const unsigned int*)ts, w1);

    precompute_mma_kernel<<<(N_NODES + 127) / 128, 256>>>(in1, in2, b1);

    int samples_per_block = 256 / 16;   // 16 samples per 256-thread block
    int blocks = (N_SAMPLES + samples_per_block - 1) / samples_per_block;
    gather_kernel<<<blocks, 256>>>(ts, w2, out, N_SAMPLES);
}